// round 12
// baseline (speedup 1.0000x reference)
#include <cuda_runtime.h>
#include <cuda_bf16.h>

// SoftmaxMarginLoss (ArcFace margin + scaled softmax CE, mean over batch).
// B=512, C=100000, fp32 logits in [-1,1), labels int32-or-int64 (sniffed).
//
// R11 hot loop (best known, 37.4us) + fully distributed epilogue:
//   2048 CTAs x 256 thr, unroll-2 strided __ldcs loop with deep L2 prefetch
//   (PF_DIST=12, predicated), packed f32x2 FMA exp2-bit-splice (no MUFU).
//   chk==0 CTA of each row pre-gathers the target logit (both label dtypes)
//   before the loop and folds the margin fixup into its partial.
//   The LAST CTA of each row (per-row atomic ticket) computes that row's
//   nll (logf included) -> g_nll[row], overlapped with other rows streaming.
//   The global last CTA only sums 512 floats and writes the mean.

#define NUM_CLASSES 100000
#define BATCH       512
#define CHUNKS      4
#define CHUNK_ELEMS (NUM_CLASSES / CHUNKS)   // 25000
#define NVEC        (CHUNK_ELEMS / 4)        // 6250 float4 per CTA
#define TPB         256
#define GRID        (BATCH * CHUNKS)         // 2048
#define PF_DIST     12                       // prefetch lead, iterations

__device__ float        g_partials[GRID];
__device__ float        g_tn[BATCH];
__device__ float        g_nll[BATCH];
__device__ unsigned int g_row_count[BATCH];  // zero-init; self-reset per replay
__device__ unsigned int g_count;             // zero-init; self-reset per replay

// ---- constants for 2^96 * exp(64x - 64) = 2^(x*K + C) ----
#define KF 92.33248261689366f                 /* 64*log2(e) */
#define CF 3.667517383106341f                 /* 96 - 64*log2(e) */
#define MAGICF 12582912.0f                    /* 1.5 * 2^23 */
#define LN2_96 66.54212933375475f             /* 96*ln(2) */

__device__ __forceinline__ unsigned long long pk2(float x) {
    unsigned int b = __float_as_uint(x);
    return ((unsigned long long)b << 32) | (unsigned long long)b;
}

struct ExpConsts {
    unsigned long long K2, C2, M2, nM2, NEG1, P3, P2, P1, P0;
};

// acc2 += 2^(x*K + C) for both packed halves. Heavy math on FFMA2.
__device__ __forceinline__ void exp2pair_acc(unsigned long long x2,
                                             unsigned long long& acc2,
                                             const ExpConsts& c)
{
    unsigned long long u2, t2, n2, f2, p2, e2;
    asm("fma.rn.f32x2 %0, %1, %2, %3;" : "=l"(u2) : "l"(x2), "l"(c.K2), "l"(c.C2));
    asm("add.rn.f32x2 %0, %1, %2;"     : "=l"(t2) : "l"(u2), "l"(c.M2));   // rne(u)+MAGIC
    asm("add.rn.f32x2 %0, %1, %2;"     : "=l"(n2) : "l"(t2), "l"(c.nM2));  // n = rne(u)
    asm("fma.rn.f32x2 %0, %1, %2, %3;" : "=l"(f2) : "l"(n2), "l"(c.NEG1), "l"(u2)); // f=u-n
    asm("fma.rn.f32x2 %0, %1, %2, %3;" : "=l"(p2) : "l"(c.P3), "l"(f2), "l"(c.P2));
    asm("fma.rn.f32x2 %0, %1, %2, %3;" : "=l"(p2) : "l"(p2), "l"(f2), "l"(c.P1));
    asm("fma.rn.f32x2 %0, %1, %2, %3;" : "=l"(p2) : "l"(p2), "l"(f2), "l"(c.P0));
    // exponent splice per half: e_bits = p_bits + (t_bits << 23)  (== p * 2^n)
    unsigned int tlo, thi, plo, phi;
    asm("mov.b64 {%0,%1}, %2;" : "=r"(tlo), "=r"(thi) : "l"(t2));
    asm("mov.b64 {%0,%1}, %2;" : "=r"(plo), "=r"(phi) : "l"(p2));
    unsigned int elo = plo + (tlo << 23);
    unsigned int ehi = phi + (thi << 23);
    asm("mov.b64 %0, {%1,%2};" : "=l"(e2) : "r"(elo), "r"(ehi));
    asm("add.rn.f32x2 %0, %1, %2;" : "=l"(acc2) : "l"(acc2), "l"(e2));
}

__device__ __forceinline__ float warp_sum(float v) {
    #pragma unroll
    for (int o = 16; o > 0; o >>= 1) v += __shfl_down_sync(0xFFFFFFFFu, v, o);
    return v;
}

// precise scalar 2^96*exp(64y-64) (MUFU exp2f fine off the hot path)
__device__ __forceinline__ float exp_s64_scaled(float y) {
    return exp2f(fmaf(y, KF, CF));
}

__device__ __forceinline__ int clampL(long long L) {
    if (L < 0) L = 0;
    if (L >= NUM_CLASSES) L = NUM_CLASSES - 1;
    return (int)L;
}

__global__ __launch_bounds__(TPB)
void fused_kernel(const float* __restrict__ logits,
                  const void*  __restrict__ labels_raw,
                  float*       __restrict__ out)
{
    const int b   = blockIdx.x;
    const int row = b >> 2;
    const int chk = b & 3;
    const float4* base =
        (const float4*)(logits + (size_t)row * NUM_CLASSES + (size_t)chk * CHUNK_ELEMS);

    __shared__ float red[TPB / 32];
    __shared__ unsigned int ticket;
    __shared__ int odd_or;

    // ---- chk==0 CTAs: sniff + both candidate gathers BEFORE the loop ----
    const int* w = (const int*)labels_raw;
    float t32 = 0.f, t64 = 0.f;
    if (chk == 0) {
        if (threadIdx.x == 0) odd_or = 0;
        __syncthreads();
        if (w[2 * threadIdx.x + 1] != 0) atomicOr(&odd_or, 1);
        if (threadIdx.x == 0) {
            const int L32 = clampL((long long)w[row]);
            const int L64 = clampL(((const long long*)labels_raw)[row]);
            t32 = logits[(size_t)row * NUM_CLASSES + L32];
            t64 = logits[(size_t)row * NUM_CLASSES + L64];
        }
    }

    ExpConsts c;
    c.K2 = pk2(KF);  c.C2 = pk2(CF);  c.M2 = pk2(MAGICF);  c.nM2 = pk2(-MAGICF);
    c.NEG1 = pk2(-1.0f);
    c.P3 = pk2(0.05550410866482158f);
    c.P2 = pk2(0.2402265069591007f);
    c.P1 = pk2(0.6931471805599453f);
    c.P0 = pk2(1.0f);

    unsigned long long ac0 = 0ull, ac1 = 0ull;
    const bool pf_lane = ((threadIdx.x & 7) == 0);   // one lane per 128B line

    #pragma unroll 2
    for (int i = threadIdx.x; i < NVEC; i += TPB) {
        const int pfi = i + PF_DIST * TPB;
        if (pf_lane && pfi < NVEC)
            asm volatile("prefetch.global.L2 [%0];" :: "l"(base + pfi));
        float4 v = __ldcs(base + i);
        unsigned long long xa, xb;
        asm("mov.b64 %0, {%1,%2};" : "=l"(xa) : "f"(v.x), "f"(v.y));
        asm("mov.b64 %0, {%1,%2};" : "=l"(xb) : "f"(v.z), "f"(v.w));
        exp2pair_acc(xa, ac0, c);
        exp2pair_acc(xb, ac1, c);
    }

    unsigned long long sA;
    asm("add.rn.f32x2 %0, %1, %2;" : "=l"(sA) : "l"(ac0), "l"(ac1));
    float a0, a1;
    asm("mov.b64 {%0,%1}, %2;" : "=f"(a0), "=f"(a1) : "l"(sA));
    float s = a0 + a1;

    s = warp_sum(s);
    const int lane = threadIdx.x & 31, wid = threadIdx.x >> 5;
    if (lane == 0) red[wid] = s;
    __syncthreads();

    if (threadIdx.x == 0) {
        float t = 0.f;
        #pragma unroll
        for (int k = 0; k < TPB / 32; k++) t += red[k];

        if (chk == 0) {
            // margin fixup for this row, folded into the partial
            const float tt = (odd_or == 0) ? t64 : t32;   // is_i64 -> t64
            const float COSM = 0.87758256189037276f;      // cos(0.5)
            const float SINM = 0.47942553860420301f;      // sin(0.5)
            const float EPS  = 1e-7f;
            float tc = fminf(fmaxf(tt, -1.0f + EPS), 1.0f - EPS);
            float tn = tc * COSM - sqrtf(fmaxf(1.0f - tc * tc, 0.0f)) * SINM;
            t += exp_s64_scaled(tn) - exp_s64_scaled(tt);
            g_tn[row] = tn;
        }
        g_partials[b] = t;
        __threadfence();

        // per-row ticket: 4th CTA of the row computes the row's nll now,
        // overlapped with the rest of the grid still streaming.
        const unsigned int rt = atomicAdd(&g_row_count[row], 1u);
        if (rt == CHUNKS - 1) {
            g_row_count[row] = 0;   // self-reset for next replay
            float S = (g_partials[4 * row] + g_partials[4 * row + 1]) +
                      (g_partials[4 * row + 2] + g_partials[4 * row + 3]);
            g_nll[row] = 64.0f + logf(S) - LN2_96 - 64.0f * g_tn[row];
            __threadfence();
        }
        ticket = atomicAdd(&g_count, 1u);
    }
    __syncthreads();
    if (ticket != GRID - 1) return;

    // ====== last block: sum 512 precomputed nll values, write mean ======
    const int i = threadIdx.x;
    float vsum = g_nll[i] + g_nll[i + TPB];

    float v = warp_sum(vsum);
    if (lane == 0) red[wid] = v;
    __syncthreads();
    if (wid == 0) {
        v = (lane < TPB / 32) ? red[lane] : 0.f;
        v = warp_sum(v);
        if (lane == 0) {
            out[0] = v * (1.0f / (float)BATCH);
            g_count = 0;   // reset for next graph replay
        }
    }
}

extern "C" void kernel_launch(void* const* d_in, const int* in_sizes, int n_in,
                              void* d_out, int out_size) {
    const float* logits = (const float*)d_in[0];
    const void*  labels = (const void*)d_in[1];
    if (n_in >= 2 && in_sizes[1] > in_sizes[0]) {   // defensive swap
        labels = (const void*)d_in[0];
        logits = (const float*)d_in[1];
    }
    fused_kernel<<<GRID, TPB>>>(logits, labels, (float*)d_out);
}

// round 13
// speedup vs baseline: 1.0968x; 1.0968x over previous
#include <cuda_runtime.h>
#include <cuda_bf16.h>

// SoftmaxMarginLoss (ArcFace margin + scaled softmax CE, mean over batch).
// B=512, C=100000, fp32 logits in [-1,1), labels int32-or-int64 (sniffed).
//
// EXACT R11 hot loop (best known, 37.4us: PF_DIST=8, clamped prefetch index,
// unroll-2 __ldcs, packed f32x2 FMA exp2-bit-splice) + distributed epilogue:
//   chk==0 CTA of each row pre-gathers the target logit (both label dtypes)
//   before the loop and folds the margin fixup into its partial.
//   The LAST CTA of each row (per-row atomic ticket) computes that row's
//   nll (logf included) -> g_nll[row], overlapped with other rows streaming.
//   The global last CTA only sums 512 floats and writes the mean.

#define NUM_CLASSES 100000
#define BATCH       512
#define CHUNKS      4
#define CHUNK_ELEMS (NUM_CLASSES / CHUNKS)   // 25000
#define NVEC        (CHUNK_ELEMS / 4)        // 6250 float4 per CTA
#define TPB         256
#define GRID        (BATCH * CHUNKS)         // 2048
#define PF_DIST     8                        // prefetch lead, iterations (R11 shape)

__device__ float        g_partials[GRID];
__device__ float        g_tn[BATCH];
__device__ float        g_nll[BATCH];
__device__ unsigned int g_row_count[BATCH];  // zero-init; self-reset per replay
__device__ unsigned int g_count;             // zero-init; self-reset per replay

// ---- constants for 2^96 * exp(64x - 64) = 2^(x*K + C) ----
#define KF 92.33248261689366f                 /* 64*log2(e) */
#define CF 3.667517383106341f                 /* 96 - 64*log2(e) */
#define MAGICF 12582912.0f                    /* 1.5 * 2^23 */
#define LN2_96 66.54212933375475f             /* 96*ln(2) */

__device__ __forceinline__ unsigned long long pk2(float x) {
    unsigned int b = __float_as_uint(x);
    return ((unsigned long long)b << 32) | (unsigned long long)b;
}

struct ExpConsts {
    unsigned long long K2, C2, M2, nM2, NEG1, P3, P2, P1, P0;
};

// acc2 += 2^(x*K + C) for both packed halves. Heavy math on FFMA2.
__device__ __forceinline__ void exp2pair_acc(unsigned long long x2,
                                             unsigned long long& acc2,
                                             const ExpConsts& c)
{
    unsigned long long u2, t2, n2, f2, p2, e2;
    asm("fma.rn.f32x2 %0, %1, %2, %3;" : "=l"(u2) : "l"(x2), "l"(c.K2), "l"(c.C2));
    asm("add.rn.f32x2 %0, %1, %2;"     : "=l"(t2) : "l"(u2), "l"(c.M2));   // rne(u)+MAGIC
    asm("add.rn.f32x2 %0, %1, %2;"     : "=l"(n2) : "l"(t2), "l"(c.nM2));  // n = rne(u)
    asm("fma.rn.f32x2 %0, %1, %2, %3;" : "=l"(f2) : "l"(n2), "l"(c.NEG1), "l"(u2)); // f=u-n
    asm("fma.rn.f32x2 %0, %1, %2, %3;" : "=l"(p2) : "l"(c.P3), "l"(f2), "l"(c.P2));
    asm("fma.rn.f32x2 %0, %1, %2, %3;" : "=l"(p2) : "l"(p2), "l"(f2), "l"(c.P1));
    asm("fma.rn.f32x2 %0, %1, %2, %3;" : "=l"(p2) : "l"(p2), "l"(f2), "l"(c.P0));
    // exponent splice per half: e_bits = p_bits + (t_bits << 23)  (== p * 2^n)
    unsigned int tlo, thi, plo, phi;
    asm("mov.b64 {%0,%1}, %2;" : "=r"(tlo), "=r"(thi) : "l"(t2));
    asm("mov.b64 {%0,%1}, %2;" : "=r"(plo), "=r"(phi) : "l"(p2));
    unsigned int elo = plo + (tlo << 23);
    unsigned int ehi = phi + (thi << 23);
    asm("mov.b64 %0, {%1,%2};" : "=l"(e2) : "r"(elo), "r"(ehi));
    asm("add.rn.f32x2 %0, %1, %2;" : "=l"(acc2) : "l"(acc2), "l"(e2));
}

__device__ __forceinline__ float warp_sum(float v) {
    #pragma unroll
    for (int o = 16; o > 0; o >>= 1) v += __shfl_down_sync(0xFFFFFFFFu, v, o);
    return v;
}

// precise scalar 2^96*exp(64y-64) (MUFU exp2f fine off the hot path)
__device__ __forceinline__ float exp_s64_scaled(float y) {
    return exp2f(fmaf(y, KF, CF));
}

__device__ __forceinline__ int clampL(long long L) {
    if (L < 0) L = 0;
    if (L >= NUM_CLASSES) L = NUM_CLASSES - 1;
    return (int)L;
}

__global__ __launch_bounds__(TPB)
void fused_kernel(const float* __restrict__ logits,
                  const void*  __restrict__ labels_raw,
                  float*       __restrict__ out)
{
    const int b   = blockIdx.x;
    const int row = b >> 2;
    const int chk = b & 3;
    const float4* base =
        (const float4*)(logits + (size_t)row * NUM_CLASSES + (size_t)chk * CHUNK_ELEMS);

    __shared__ float red[TPB / 32];
    __shared__ unsigned int ticket;
    __shared__ int odd_or;

    // ---- chk==0 CTAs: sniff + both candidate gathers BEFORE the loop ----
    const int* w = (const int*)labels_raw;
    float t32 = 0.f, t64 = 0.f;
    if (chk == 0) {
        if (threadIdx.x == 0) odd_or = 0;
        __syncthreads();
        if (w[2 * threadIdx.x + 1] != 0) atomicOr(&odd_or, 1);
        if (threadIdx.x == 0) {
            const int L32 = clampL((long long)w[row]);
            const int L64 = clampL(((const long long*)labels_raw)[row]);
            t32 = logits[(size_t)row * NUM_CLASSES + L32];
            t64 = logits[(size_t)row * NUM_CLASSES + L64];
        }
    }

    ExpConsts c;
    c.K2 = pk2(KF);  c.C2 = pk2(CF);  c.M2 = pk2(MAGICF);  c.nM2 = pk2(-MAGICF);
    c.NEG1 = pk2(-1.0f);
    c.P3 = pk2(0.05550410866482158f);
    c.P2 = pk2(0.2402265069591007f);
    c.P1 = pk2(0.6931471805599453f);
    c.P0 = pk2(1.0f);

    unsigned long long ac0 = 0ull, ac1 = 0ull;
    const bool pf_lane = ((threadIdx.x & 7) == 0);   // one lane per 128B line

    // ---- EXACT R11 hot loop shape ----
    #pragma unroll 2
    for (int i = threadIdx.x; i < NVEC; i += TPB) {
        int pfi = i + PF_DIST * TPB;
        if (pfi > NVEC - 1) pfi = NVEC - 1;          // clamp inside the chunk
        if (pf_lane)
            asm volatile("prefetch.global.L2 [%0];" :: "l"(base + pfi));
        float4 v = __ldcs(base + i);
        unsigned long long xa, xb;
        asm("mov.b64 %0, {%1,%2};" : "=l"(xa) : "f"(v.x), "f"(v.y));
        asm("mov.b64 %0, {%1,%2};" : "=l"(xb) : "f"(v.z), "f"(v.w));
        exp2pair_acc(xa, ac0, c);
        exp2pair_acc(xb, ac1, c);
    }

    unsigned long long sA;
    asm("add.rn.f32x2 %0, %1, %2;" : "=l"(sA) : "l"(ac0), "l"(ac1));
    float a0, a1;
    asm("mov.b64 {%0,%1}, %2;" : "=f"(a0), "=f"(a1) : "l"(sA));
    float s = a0 + a1;

    s = warp_sum(s);
    const int lane = threadIdx.x & 31, wid = threadIdx.x >> 5;
    if (lane == 0) red[wid] = s;
    __syncthreads();

    if (threadIdx.x == 0) {
        float t = 0.f;
        #pragma unroll
        for (int k = 0; k < TPB / 32; k++) t += red[k];

        if (chk == 0) {
            // margin fixup for this row, folded into the partial
            const float tt = (odd_or == 0) ? t64 : t32;   // is_i64 -> t64
            const float COSM = 0.87758256189037276f;      // cos(0.5)
            const float SINM = 0.47942553860420301f;      // sin(0.5)
            const float EPS  = 1e-7f;
            float tc = fminf(fmaxf(tt, -1.0f + EPS), 1.0f - EPS);
            float tn = tc * COSM - sqrtf(fmaxf(1.0f - tc * tc, 0.0f)) * SINM;
            t += exp_s64_scaled(tn) - exp_s64_scaled(tt);
            g_tn[row] = tn;
        }
        g_partials[b] = t;
        __threadfence();

        // per-row ticket: 4th CTA of the row computes the row's nll now,
        // overlapped with the rest of the grid still streaming.
        const unsigned int rt = atomicAdd(&g_row_count[row], 1u);
        if (rt == CHUNKS - 1) {
            g_row_count[row] = 0;   // self-reset for next replay
            float S = (g_partials[4 * row] + g_partials[4 * row + 1]) +
                      (g_partials[4 * row + 2] + g_partials[4 * row + 3]);
            g_nll[row] = 64.0f + logf(S) - LN2_96 - 64.0f * g_tn[row];
            __threadfence();
        }
        ticket = atomicAdd(&g_count, 1u);
    }
    __syncthreads();
    if (ticket != GRID - 1) return;

    // ====== last block: sum 512 precomputed nll values, write mean ======
    const int i = threadIdx.x;
    float vsum = g_nll[i] + g_nll[i + TPB];

    float v = warp_sum(vsum);
    if (lane == 0) red[wid] = v;
    __syncthreads();
    if (wid == 0) {
        v = (lane < TPB / 32) ? red[lane] : 0.f;
        v = warp_sum(v);
        if (lane == 0) {
            out[0] = v * (1.0f / (float)BATCH);
            g_count = 0;   // reset for next graph replay
        }
    }
}

extern "C" void kernel_launch(void* const* d_in, const int* in_sizes, int n_in,
                              void* d_out, int out_size) {
    const float* logits = (const float*)d_in[0];
    const void*  labels = (const void*)d_in[1];
    if (n_in >= 2 && in_sizes[1] > in_sizes[0]) {   // defensive swap
        labels = (const void*)d_in[0];
        logits = (const float*)d_in[1];
    }
    fused_kernel<<<GRID, TPB>>>(logits, labels, (float*)d_out);
}

// round 14
// speedup vs baseline: 1.1624x; 1.0598x over previous
#include <cuda_runtime.h>
#include <cuda_bf16.h>

// SoftmaxMarginLoss (ArcFace margin + scaled softmax CE, mean over batch).
// B=512, C=100000, fp32 logits in [-1,1), labels int32-or-int64 (sniffed).
//
// FINAL (== R11, verified 37.4us): single fused kernel.
//   2048 CTAs x 256 thr, unroll-2 strided __ldcs loop with deep L2 prefetch
//   (PF_DIST=8, clamped index, one prefetch lane per 128B line), packed
//   f32x2 FMA (FFMA2) exp2-by-bit-splice summation of 2^96*exp(64x-64)
//   (single pass, no max pass, no MUFU in the hot loop).
//   Each row's chk==0 CTA sniffs the label dtype and issues both candidate
//   target-logit gathers BEFORE the main loop (they complete under it), then
//   folds the ArcFace margin-fixup delta into its partial and stores tn.
//   Global last CTA (atomic ticket) sums partials, logf, NLL, mean -> out[0].

#define NUM_CLASSES 100000
#define BATCH       512
#define CHUNKS      4
#define CHUNK_ELEMS (NUM_CLASSES / CHUNKS)   // 25000
#define NVEC        (CHUNK_ELEMS / 4)        // 6250 float4 per CTA
#define TPB         256
#define GRID        (BATCH * CHUNKS)         // 2048
#define PF_DIST     8                        // prefetch lead, iterations

__device__ float        g_partials[GRID];
__device__ float        g_tn[BATCH];
__device__ unsigned int g_count;             // zero-init; self-resets each run

// ---- constants for 2^96 * exp(64x - 64) = 2^(x*K + C) ----
#define KF 92.33248261689366f                 /* 64*log2(e) */
#define CF 3.667517383106341f                 /* 96 - 64*log2(e) */
#define MAGICF 12582912.0f                    /* 1.5 * 2^23 */
#define LN2_96 66.54212933375475f             /* 96*ln(2) */

__device__ __forceinline__ unsigned long long pk2(float x) {
    unsigned int b = __float_as_uint(x);
    return ((unsigned long long)b << 32) | (unsigned long long)b;
}

struct ExpConsts {
    unsigned long long K2, C2, M2, nM2, NEG1, P3, P2, P1, P0;
};

// acc2 += 2^(x*K + C) for both packed halves. Heavy math on FFMA2.
__device__ __forceinline__ void exp2pair_acc(unsigned long long x2,
                                             unsigned long long& acc2,
                                             const ExpConsts& c)
{
    unsigned long long u2, t2, n2, f2, p2, e2;
    asm("fma.rn.f32x2 %0, %1, %2, %3;" : "=l"(u2) : "l"(x2), "l"(c.K2), "l"(c.C2));
    asm("add.rn.f32x2 %0, %1, %2;"     : "=l"(t2) : "l"(u2), "l"(c.M2));   // rne(u)+MAGIC
    asm("add.rn.f32x2 %0, %1, %2;"     : "=l"(n2) : "l"(t2), "l"(c.nM2));  // n = rne(u)
    asm("fma.rn.f32x2 %0, %1, %2, %3;" : "=l"(f2) : "l"(n2), "l"(c.NEG1), "l"(u2)); // f=u-n
    asm("fma.rn.f32x2 %0, %1, %2, %3;" : "=l"(p2) : "l"(c.P3), "l"(f2), "l"(c.P2));
    asm("fma.rn.f32x2 %0, %1, %2, %3;" : "=l"(p2) : "l"(p2), "l"(f2), "l"(c.P1));
    asm("fma.rn.f32x2 %0, %1, %2, %3;" : "=l"(p2) : "l"(p2), "l"(f2), "l"(c.P0));
    // exponent splice per half: e_bits = p_bits + (t_bits << 23)  (== p * 2^n)
    unsigned int tlo, thi, plo, phi;
    asm("mov.b64 {%0,%1}, %2;" : "=r"(tlo), "=r"(thi) : "l"(t2));
    asm("mov.b64 {%0,%1}, %2;" : "=r"(plo), "=r"(phi) : "l"(p2));
    unsigned int elo = plo + (tlo << 23);
    unsigned int ehi = phi + (thi << 23);
    asm("mov.b64 %0, {%1,%2};" : "=l"(e2) : "r"(elo), "r"(ehi));
    asm("add.rn.f32x2 %0, %1, %2;" : "=l"(acc2) : "l"(acc2), "l"(e2));
}

__device__ __forceinline__ float warp_sum(float v) {
    #pragma unroll
    for (int o = 16; o > 0; o >>= 1) v += __shfl_down_sync(0xFFFFFFFFu, v, o);
    return v;
}

// precise scalar 2^96*exp(64y-64) (MUFU exp2f fine off the hot path)
__device__ __forceinline__ float exp_s64_scaled(float y) {
    return exp2f(fmaf(y, KF, CF));
}

__device__ __forceinline__ int clampL(long long L) {
    if (L < 0) L = 0;
    if (L >= NUM_CLASSES) L = NUM_CLASSES - 1;
    return (int)L;
}

__global__ __launch_bounds__(TPB)
void fused_kernel(const float* __restrict__ logits,
                  const void*  __restrict__ labels_raw,
                  float*       __restrict__ out)
{
    const int b   = blockIdx.x;
    const int row = b >> 2;
    const int chk = b & 3;
    const float4* base =
        (const float4*)(logits + (size_t)row * NUM_CLASSES + (size_t)chk * CHUNK_ELEMS);

    __shared__ float red[TPB / 32];
    __shared__ unsigned int ticket;
    __shared__ int odd_or;

    // ---- chk==0 CTAs: start sniff + both candidate gathers BEFORE the loop ----
    const int* w = (const int*)labels_raw;
    float t32 = 0.f, t64 = 0.f;
    if (chk == 0) {
        if (threadIdx.x == 0) odd_or = 0;
        __syncthreads();
        if (w[2 * threadIdx.x + 1] != 0) atomicOr(&odd_or, 1);
        if (threadIdx.x == 0) {
            const int L32 = clampL((long long)w[row]);
            const int L64 = clampL(((const long long*)labels_raw)[row]);
            t32 = logits[(size_t)row * NUM_CLASSES + L32];
            t64 = logits[(size_t)row * NUM_CLASSES + L64];
        }
    }

    ExpConsts c;
    c.K2 = pk2(KF);  c.C2 = pk2(CF);  c.M2 = pk2(MAGICF);  c.nM2 = pk2(-MAGICF);
    c.NEG1 = pk2(-1.0f);
    c.P3 = pk2(0.05550410866482158f);
    c.P2 = pk2(0.2402265069591007f);
    c.P1 = pk2(0.6931471805599453f);
    c.P0 = pk2(1.0f);

    unsigned long long ac0 = 0ull, ac1 = 0ull;
    const bool pf_lane = ((threadIdx.x & 7) == 0);   // one lane per 128B line

    #pragma unroll 2
    for (int i = threadIdx.x; i < NVEC; i += TPB) {
        int pfi = i + PF_DIST * TPB;
        if (pfi > NVEC - 1) pfi = NVEC - 1;          // clamp inside the chunk
        if (pf_lane)
            asm volatile("prefetch.global.L2 [%0];" :: "l"(base + pfi));
        float4 v = __ldcs(base + i);
        unsigned long long xa, xb;
        asm("mov.b64 %0, {%1,%2};" : "=l"(xa) : "f"(v.x), "f"(v.y));
        asm("mov.b64 %0, {%1,%2};" : "=l"(xb) : "f"(v.z), "f"(v.w));
        exp2pair_acc(xa, ac0, c);
        exp2pair_acc(xb, ac1, c);
    }

    unsigned long long sA;
    asm("add.rn.f32x2 %0, %1, %2;" : "=l"(sA) : "l"(ac0), "l"(ac1));
    float a0, a1;
    asm("mov.b64 {%0,%1}, %2;" : "=f"(a0), "=f"(a1) : "l"(sA));
    float s = a0 + a1;

    s = warp_sum(s);
    const int lane = threadIdx.x & 31, wid = threadIdx.x >> 5;
    if (lane == 0) red[wid] = s;
    __syncthreads();
    if (threadIdx.x == 0) {
        float t = 0.f;
        #pragma unroll
        for (int k = 0; k < TPB / 32; k++) t += red[k];

        if (chk == 0) {
            // margin fixup for this row, folded into the partial
            const float tt = (odd_or == 0) ? t64 : t32;   // is_i64 -> t64
            const float COSM = 0.87758256189037276f;      // cos(0.5)
            const float SINM = 0.47942553860420301f;      // sin(0.5)
            const float EPS  = 1e-7f;
            float tc = fminf(fmaxf(tt, -1.0f + EPS), 1.0f - EPS);
            float tn = tc * COSM - sqrtf(fmaxf(1.0f - tc * tc, 0.0f)) * SINM;
            t += exp_s64_scaled(tn) - exp_s64_scaled(tt);
            g_tn[row] = tn;
        }
        g_partials[b] = t;
        __threadfence();
        ticket = atomicAdd(&g_count, 1u);
    }
    __syncthreads();
    if (ticket != GRID - 1) return;

    // ====== last block: pure reduction (no gathers, no sniff) ======
    const int i = threadIdx.x;
    float vsum = 0.f;
    #pragma unroll
    for (int rr = 0; rr < BATCH / TPB; rr++) {
        const int r = i + rr * TPB;
        float S = (g_partials[4 * r] + g_partials[4 * r + 1]) +
                  (g_partials[4 * r + 2] + g_partials[4 * r + 3]);
        // nll = 64 + log(S) - 96*ln2 - 64*tn
        vsum += 64.0f + logf(S) - LN2_96 - 64.0f * g_tn[r];
    }

    float v = warp_sum(vsum);
    if (lane == 0) red[wid] = v;
    __syncthreads();
    if (wid == 0) {
        v = (lane < TPB / 32) ? red[lane] : 0.f;
        v = warp_sum(v);
        if (lane == 0) {
            out[0] = v * (1.0f / (float)BATCH);
            g_count = 0;   // reset for next graph replay
        }
    }
}

extern "C" void kernel_launch(void* const* d_in, const int* in_sizes, int n_in,
                              void* d_out, int out_size) {
    const float* logits = (const float*)d_in[0];
    const void*  labels = (const void*)d_in[1];
    if (n_in >= 2 && in_sizes[1] > in_sizes[0]) {   // defensive swap
        labels = (const void*)d_in[0];
        logits = (const float*)d_in[1];
    }
    fused_kernel<<<GRID, TPB>>>(logits, labels, (float*)d_out);
}

// round 15
// speedup vs baseline: 1.1775x; 1.0130x over previous
#include <cuda_runtime.h>
#include <cuda_bf16.h>

// SoftmaxMarginLoss (ArcFace margin + scaled softmax CE, mean over batch).
// B=512, C=100000, fp32 logits in [-1,1), labels int32-or-int64 (sniffed).
//
// R11 kernel (verified 37.4us) with ONE change: CHUNKS 4 -> 2, i.e.
// GRID=1024 CTAs <= 1184 concurrent slots -> a SINGLE co-resident wave
// (removes the 0.73-fill second wave + drain tail). Loop shape, prefetch,
// math, and epilogue structure are otherwise identical.

#define NUM_CLASSES 100000
#define BATCH       512
#define CHUNKS      2
#define CHUNK_ELEMS (NUM_CLASSES / CHUNKS)   // 50000
#define NVEC        (CHUNK_ELEMS / 4)        // 12500 float4 per CTA
#define TPB         256
#define GRID        (BATCH * CHUNKS)         // 1024
#define PF_DIST     8                        // prefetch lead, iterations

__device__ float        g_partials[GRID];
__device__ float        g_tn[BATCH];
__device__ unsigned int g_count;             // zero-init; self-resets each run

// ---- constants for 2^96 * exp(64x - 64) = 2^(x*K + C) ----
#define KF 92.33248261689366f                 /* 64*log2(e) */
#define CF 3.667517383106341f                 /* 96 - 64*log2(e) */
#define MAGICF 12582912.0f                    /* 1.5 * 2^23 */
#define LN2_96 66.54212933375475f             /* 96*ln(2) */

__device__ __forceinline__ unsigned long long pk2(float x) {
    unsigned int b = __float_as_uint(x);
    return ((unsigned long long)b << 32) | (unsigned long long)b;
}

struct ExpConsts {
    unsigned long long K2, C2, M2, nM2, NEG1, P3, P2, P1, P0;
};

// acc2 += 2^(x*K + C) for both packed halves. Heavy math on FFMA2.
__device__ __forceinline__ void exp2pair_acc(unsigned long long x2,
                                             unsigned long long& acc2,
                                             const ExpConsts& c)
{
    unsigned long long u2, t2, n2, f2, p2, e2;
    asm("fma.rn.f32x2 %0, %1, %2, %3;" : "=l"(u2) : "l"(x2), "l"(c.K2), "l"(c.C2));
    asm("add.rn.f32x2 %0, %1, %2;"     : "=l"(t2) : "l"(u2), "l"(c.M2));   // rne(u)+MAGIC
    asm("add.rn.f32x2 %0, %1, %2;"     : "=l"(n2) : "l"(t2), "l"(c.nM2));  // n = rne(u)
    asm("fma.rn.f32x2 %0, %1, %2, %3;" : "=l"(f2) : "l"(n2), "l"(c.NEG1), "l"(u2)); // f=u-n
    asm("fma.rn.f32x2 %0, %1, %2, %3;" : "=l"(p2) : "l"(c.P3), "l"(f2), "l"(c.P2));
    asm("fma.rn.f32x2 %0, %1, %2, %3;" : "=l"(p2) : "l"(p2), "l"(f2), "l"(c.P1));
    asm("fma.rn.f32x2 %0, %1, %2, %3;" : "=l"(p2) : "l"(p2), "l"(f2), "l"(c.P0));
    // exponent splice per half: e_bits = p_bits + (t_bits << 23)  (== p * 2^n)
    unsigned int tlo, thi, plo, phi;
    asm("mov.b64 {%0,%1}, %2;" : "=r"(tlo), "=r"(thi) : "l"(t2));
    asm("mov.b64 {%0,%1}, %2;" : "=r"(plo), "=r"(phi) : "l"(p2));
    unsigned int elo = plo + (tlo << 23);
    unsigned int ehi = phi + (thi << 23);
    asm("mov.b64 %0, {%1,%2};" : "=l"(e2) : "r"(elo), "r"(ehi));
    asm("add.rn.f32x2 %0, %1, %2;" : "=l"(acc2) : "l"(acc2), "l"(e2));
}

__device__ __forceinline__ float warp_sum(float v) {
    #pragma unroll
    for (int o = 16; o > 0; o >>= 1) v += __shfl_down_sync(0xFFFFFFFFu, v, o);
    return v;
}

// precise scalar 2^96*exp(64y-64) (MUFU exp2f fine off the hot path)
__device__ __forceinline__ float exp_s64_scaled(float y) {
    return exp2f(fmaf(y, KF, CF));
}

__device__ __forceinline__ int clampL(long long L) {
    if (L < 0) L = 0;
    if (L >= NUM_CLASSES) L = NUM_CLASSES - 1;
    return (int)L;
}

__global__ __launch_bounds__(TPB)
void fused_kernel(const float* __restrict__ logits,
                  const void*  __restrict__ labels_raw,
                  float*       __restrict__ out)
{
    const int b   = blockIdx.x;
    const int row = b >> 1;
    const int chk = b & 1;
    const float4* base =
        (const float4*)(logits + (size_t)row * NUM_CLASSES + (size_t)chk * CHUNK_ELEMS);

    __shared__ float red[TPB / 32];
    __shared__ unsigned int ticket;
    __shared__ int odd_or;

    // ---- chk==0 CTAs: start sniff + both candidate gathers BEFORE the loop ----
    const int* w = (const int*)labels_raw;
    float t32 = 0.f, t64 = 0.f;
    if (chk == 0) {
        if (threadIdx.x == 0) odd_or = 0;
        __syncthreads();
        if (w[2 * threadIdx.x + 1] != 0) atomicOr(&odd_or, 1);
        if (threadIdx.x == 0) {
            const int L32 = clampL((long long)w[row]);
            const int L64 = clampL(((const long long*)labels_raw)[row]);
            t32 = logits[(size_t)row * NUM_CLASSES + L32];
            t64 = logits[(size_t)row * NUM_CLASSES + L64];
        }
    }

    ExpConsts c;
    c.K2 = pk2(KF);  c.C2 = pk2(CF);  c.M2 = pk2(MAGICF);  c.nM2 = pk2(-MAGICF);
    c.NEG1 = pk2(-1.0f);
    c.P3 = pk2(0.05550410866482158f);
    c.P2 = pk2(0.2402265069591007f);
    c.P1 = pk2(0.6931471805599453f);
    c.P0 = pk2(1.0f);

    unsigned long long ac0 = 0ull, ac1 = 0ull;
    const bool pf_lane = ((threadIdx.x & 7) == 0);   // one lane per 128B line

    #pragma unroll 2
    for (int i = threadIdx.x; i < NVEC; i += TPB) {
        int pfi = i + PF_DIST * TPB;
        if (pfi > NVEC - 1) pfi = NVEC - 1;          // clamp inside the chunk
        if (pf_lane)
            asm volatile("prefetch.global.L2 [%0];" :: "l"(base + pfi));
        float4 v = __ldcs(base + i);
        unsigned long long xa, xb;
        asm("mov.b64 %0, {%1,%2};" : "=l"(xa) : "f"(v.x), "f"(v.y));
        asm("mov.b64 %0, {%1,%2};" : "=l"(xb) : "f"(v.z), "f"(v.w));
        exp2pair_acc(xa, ac0, c);
        exp2pair_acc(xb, ac1, c);
    }

    unsigned long long sA;
    asm("add.rn.f32x2 %0, %1, %2;" : "=l"(sA) : "l"(ac0), "l"(ac1));
    float a0, a1;
    asm("mov.b64 {%0,%1}, %2;" : "=f"(a0), "=f"(a1) : "l"(sA));
    float s = a0 + a1;

    s = warp_sum(s);
    const int lane = threadIdx.x & 31, wid = threadIdx.x >> 5;
    if (lane == 0) red[wid] = s;
    __syncthreads();
    if (threadIdx.x == 0) {
        float t = 0.f;
        #pragma unroll
        for (int k = 0; k < TPB / 32; k++) t += red[k];

        if (chk == 0) {
            // margin fixup for this row, folded into the partial
            const float tt = (odd_or == 0) ? t64 : t32;   // is_i64 -> t64
            const float COSM = 0.87758256189037276f;      // cos(0.5)
            const float SINM = 0.47942553860420301f;      // sin(0.5)
            const float EPS  = 1e-7f;
            float tc = fminf(fmaxf(tt, -1.0f + EPS), 1.0f - EPS);
            float tn = tc * COSM - sqrtf(fmaxf(1.0f - tc * tc, 0.0f)) * SINM;
            t += exp_s64_scaled(tn) - exp_s64_scaled(tt);
            g_tn[row] = tn;
        }
        g_partials[b] = t;
        __threadfence();
        ticket = atomicAdd(&g_count, 1u);
    }
    __syncthreads();
    if (ticket != GRID - 1) return;

    // ====== last block: pure reduction (no gathers, no sniff) ======
    const int i = threadIdx.x;
    float vsum = 0.f;
    #pragma unroll
    for (int rr = 0; rr < BATCH / TPB; rr++) {
        const int r = i + rr * TPB;
        float S = g_partials[2 * r] + g_partials[2 * r + 1];
        // nll = 64 + log(S) - 96*ln2 - 64*tn
        vsum += 64.0f + logf(S) - LN2_96 - 64.0f * g_tn[r];
    }

    float v = warp_sum(vsum);
    if (lane == 0) red[wid] = v;
    __syncthreads();
    if (wid == 0) {
        v = (lane < TPB / 32) ? red[lane] : 0.f;
        v = warp_sum(v);
        if (lane == 0) {
            out[0] = v * (1.0f / (float)BATCH);
            g_count = 0;   // reset for next graph replay
        }
    }
}

extern "C" void kernel_launch(void* const* d_in, const int* in_sizes, int n_in,
                              void* d_out, int out_size) {
    const float* logits = (const float*)d_in[0];
    const void*  labels = (const void*)d_in[1];
    if (n_in >= 2 && in_sizes[1] > in_sizes[0]) {   // defensive swap
        labels = (const void*)d_in[0];
        logits = (const float*)d_in[1];
    }
    fused_kernel<<<GRID, TPB>>>(logits, labels, (float*)d_out);
}